// round 3
// baseline (speedup 1.0000x reference)
#include <cuda_runtime.h>

#define BATCH 16
#define CIN   1024
#define CPD   512
#define SS    1024   // H*W = 32*32

#define BM 128
#define BN 128
#define BK 16
#define TM 8
#define TN 8

// ---------------- scratch (device globals; no allocation) ----------------
__device__ float  d_t[(size_t)BATCH * CPD * SS];   // t = Wt x
__device__ float  d_p[(size_t)BATCH * CPD * SS];   // p = Wp x
__device__ float  d_g[(size_t)BATCH * CPD * SS];   // g = Wg x
__device__ float  d_z[(size_t)BATCH * CIN * SS];   // z = Wz y
__device__ double d_red[BATCH][8];                 // [0..2]=Sg,Spg,Sp2g  [3]=sum z [4]=sum z^2

__global__ void zero_red_kernel() {
    int i = threadIdx.x;
    if (i < BATCH * 8) ((double*)d_red)[i] = 0.0;
}

// ---------------- GEMM 1: t/p/g = {Wt,Wp,Wg} @ X_b ----------------
// A: [512,1024] row-major (one of 3 weights, selected by m-tile), B: x[b] [1024,1024]
__global__ __launch_bounds__(256) void gemm_tpg_kernel(
    const float* __restrict__ Wt, const float* __restrict__ Wp,
    const float* __restrict__ Wg, const float* __restrict__ x)
{
    __shared__ float As[BK][BM + 4];
    __shared__ float Bs[BK][BN];

    const int b   = blockIdx.z;
    const int mt  = blockIdx.x;          // 0..11
    const int nt  = blockIdx.y;          // 0..7
    const int mat = mt >> 2;             // 0:t 1:p 2:g
    const int row0 = (mt & 3) * BM;

    const float* W = (mat == 0) ? Wt : ((mat == 1) ? Wp : Wg);
    const float* A = W + (size_t)row0 * CIN;
    const float* B = x + (size_t)b * CIN * SS + nt * BN;
    float* Cbase = (mat == 0) ? d_t : ((mat == 1) ? d_p : d_g);
    float* Cout  = Cbase + (size_t)b * CPD * SS + (size_t)row0 * SS + nt * BN;

    const int tid = threadIdx.x;
    const int ar = tid >> 2;            // 0..63
    const int ac = (tid & 3) << 2;      // 0,4,8,12
    const int br = tid >> 5;            // 0..7
    const int bc = (tid & 31) << 2;
    const int ty = tid >> 4, tx = tid & 15;

    float acc[TM][TN];
#pragma unroll
    for (int i = 0; i < TM; i++)
#pragma unroll
        for (int j = 0; j < TN; j++) acc[i][j] = 0.f;

    for (int k0 = 0; k0 < CIN; k0 += BK) {
#pragma unroll
        for (int h = 0; h < 2; h++) {
            float4 v = *(const float4*)(A + (size_t)(ar + h * 64) * CIN + k0 + ac);
            As[ac + 0][ar + h * 64] = v.x;
            As[ac + 1][ar + h * 64] = v.y;
            As[ac + 2][ar + h * 64] = v.z;
            As[ac + 3][ar + h * 64] = v.w;
        }
#pragma unroll
        for (int h = 0; h < 2; h++) {
            float4 v = *(const float4*)(B + (size_t)(k0 + br + h * 8) * SS + bc);
            *(float4*)(&Bs[br + h * 8][bc]) = v;
        }
        __syncthreads();
#pragma unroll
        for (int kk = 0; kk < BK; kk++) {
            float a[TM], bb[TN];
            float4 a0 = *(const float4*)(&As[kk][ty * TM]);
            float4 a1 = *(const float4*)(&As[kk][ty * TM + 4]);
            a[0]=a0.x; a[1]=a0.y; a[2]=a0.z; a[3]=a0.w;
            a[4]=a1.x; a[5]=a1.y; a[6]=a1.z; a[7]=a1.w;
            float4 b0 = *(const float4*)(&Bs[kk][tx * TN]);
            float4 b1 = *(const float4*)(&Bs[kk][tx * TN + 4]);
            bb[0]=b0.x; bb[1]=b0.y; bb[2]=b0.z; bb[3]=b0.w;
            bb[4]=b1.x; bb[5]=b1.y; bb[6]=b1.z; bb[7]=b1.w;
#pragma unroll
            for (int i = 0; i < TM; i++)
#pragma unroll
                for (int j = 0; j < TN; j++) acc[i][j] += a[i] * bb[j];
        }
        __syncthreads();
    }
#pragma unroll
    for (int i = 0; i < TM; i++) {
        float4 v0 = {acc[i][0], acc[i][1], acc[i][2], acc[i][3]};
        float4 v1 = {acc[i][4], acc[i][5], acc[i][6], acc[i][7]};
        *(float4*)(Cout + (size_t)(ty * TM + i) * SS + tx * TN)     = v0;
        *(float4*)(Cout + (size_t)(ty * TM + i) * SS + tx * TN + 4) = v1;
    }
}

// ---------------- reduction: Sg, Spg, Sp2g per batch ----------------
__global__ void reduce_pg_kernel() {
    const int b = blockIdx.y;
    const float* p = d_p + (size_t)b * CPD * SS;
    const float* g = d_g + (size_t)b * CPD * SS;
    const int n = CPD * SS;
    double s0 = 0, s1 = 0, s2 = 0;
    for (int i = blockIdx.x * blockDim.x + threadIdx.x; i < n; i += gridDim.x * blockDim.x) {
        float pv = p[i], gv = g[i];
        s0 += (double)gv;
        s1 += (double)pv * gv;
        s2 += (double)pv * pv * gv;
    }
    __shared__ double sh0[256], sh1[256], sh2[256];
    sh0[threadIdx.x] = s0; sh1[threadIdx.x] = s1; sh2[threadIdx.x] = s2;
    __syncthreads();
    for (int off = 128; off > 0; off >>= 1) {
        if (threadIdx.x < off) {
            sh0[threadIdx.x] += sh0[threadIdx.x + off];
            sh1[threadIdx.x] += sh1[threadIdx.x + off];
            sh2[threadIdx.x] += sh2[threadIdx.x + off];
        }
        __syncthreads();
    }
    if (threadIdx.x == 0) {
        atomicAdd(&d_red[b][0], sh0[0]);
        atomicAdd(&d_red[b][1], sh1[0]);
        atomicAdd(&d_red[b][2], sh2[0]);
    }
}

// ---------------- GEMM 2: z = Wz @ y,  y = c0 + c1 t + c2 t^2 (on the fly) ----------------
// Fused GroupNorm sum reduction in epilogue.
__global__ __launch_bounds__(256) void gemm_z_kernel(const float* __restrict__ Wz)
{
    __shared__ float As[BK][BM + 4];
    __shared__ float Bs[BK][BN];

    const int b    = blockIdx.z;
    const int row0 = blockIdx.x * BM;
    const int nt   = blockIdx.y;

    const double BETA = 0.9998000199986667;   // exp(-2*GAMMA), GAMMA=1e-4
    const float c0 = (float)(BETA * d_red[b][0]);
    const float c1 = (float)(2e-4 * BETA * d_red[b][1]);
    const float c2 = (float)(2e-8 * BETA * d_red[b][2]);

    const float* A  = Wz + (size_t)row0 * CPD;
    const float* Bt = d_t + (size_t)b * CPD * SS + nt * BN;
    float* Cout = d_z + (size_t)b * CIN * SS + (size_t)row0 * SS + nt * BN;

    const int tid = threadIdx.x;
    const int ar = tid >> 2;
    const int ac = (tid & 3) << 2;
    const int br = tid >> 5;
    const int bc = (tid & 31) << 2;
    const int ty = tid >> 4, tx = tid & 15;

    float acc[TM][TN];
#pragma unroll
    for (int i = 0; i < TM; i++)
#pragma unroll
        for (int j = 0; j < TN; j++) acc[i][j] = 0.f;

    for (int k0 = 0; k0 < CPD; k0 += BK) {
#pragma unroll
        for (int h = 0; h < 2; h++) {
            float4 v = *(const float4*)(A + (size_t)(ar + h * 64) * CPD + k0 + ac);
            As[ac + 0][ar + h * 64] = v.x;
            As[ac + 1][ar + h * 64] = v.y;
            As[ac + 2][ar + h * 64] = v.z;
            As[ac + 3][ar + h * 64] = v.w;
        }
#pragma unroll
        for (int h = 0; h < 2; h++) {
            float4 v = *(const float4*)(Bt + (size_t)(k0 + br + h * 8) * SS + bc);
            // y = c0 + t*(c1 + c2*t)
            v.x = c0 + v.x * (c1 + c2 * v.x);
            v.y = c0 + v.y * (c1 + c2 * v.y);
            v.z = c0 + v.z * (c1 + c2 * v.z);
            v.w = c0 + v.w * (c1 + c2 * v.w);
            *(float4*)(&Bs[br + h * 8][bc]) = v;
        }
        __syncthreads();
#pragma unroll
        for (int kk = 0; kk < BK; kk++) {
            float a[TM], bb[TN];
            float4 a0 = *(const float4*)(&As[kk][ty * TM]);
            float4 a1 = *(const float4*)(&As[kk][ty * TM + 4]);
            a[0]=a0.x; a[1]=a0.y; a[2]=a0.z; a[3]=a0.w;
            a[4]=a1.x; a[5]=a1.y; a[6]=a1.z; a[7]=a1.w;
            float4 b0 = *(const float4*)(&Bs[kk][tx * TN]);
            float4 b1 = *(const float4*)(&Bs[kk][tx * TN + 4]);
            bb[0]=b0.x; bb[1]=b0.y; bb[2]=b0.z; bb[3]=b0.w;
            bb[4]=b1.x; bb[5]=b1.y; bb[6]=b1.z; bb[7]=b1.w;
#pragma unroll
            for (int i = 0; i < TM; i++)
#pragma unroll
                for (int j = 0; j < TN; j++) acc[i][j] += a[i] * bb[j];
        }
        __syncthreads();
    }

    double zs = 0.0, zq = 0.0;
#pragma unroll
    for (int i = 0; i < TM; i++) {
#pragma unroll
        for (int j = 0; j < TN; j++) {
            float v = acc[i][j];
            zs += (double)v;
            zq += (double)v * v;
        }
        float4 v0 = {acc[i][0], acc[i][1], acc[i][2], acc[i][3]};
        float4 v1 = {acc[i][4], acc[i][5], acc[i][6], acc[i][7]};
        *(float4*)(Cout + (size_t)(ty * TM + i) * SS + tx * TN)     = v0;
        *(float4*)(Cout + (size_t)(ty * TM + i) * SS + tx * TN + 4) = v1;
    }

    __shared__ double shs[256], shq[256];
    shs[tid] = zs; shq[tid] = zq;
    __syncthreads();
    for (int off = 128; off > 0; off >>= 1) {
        if (tid < off) {
            shs[tid] += shs[tid + off];
            shq[tid] += shq[tid + off];
        }
        __syncthreads();
    }
    if (tid == 0) {
        atomicAdd(&d_red[b][3], shs[0]);
        atomicAdd(&d_red[b][4], shq[0]);
    }
}

// ---------------- finalize: out = (z - mu)*rsigma*gn_w + gn_b + x ----------------
__global__ void finalize_kernel(const float* __restrict__ x,
                                const float* __restrict__ gnw,
                                const float* __restrict__ gnb,
                                float* __restrict__ out)
{
    size_t idx4 = (size_t)blockIdx.x * blockDim.x + threadIdx.x;
    const size_t total4 = (size_t)BATCH * CIN * SS / 4;
    if (idx4 >= total4) return;
    size_t idx = idx4 * 4;
    int b = (int)(idx / ((size_t)CIN * SS));
    int c = (int)((idx / SS) % CIN);

    const double n = (double)CIN * SS;
    double mu  = d_red[b][3] / n;
    double var = d_red[b][4] / n - mu * mu;
    float rs  = rsqrtf((float)var + 1e-5f);
    float fmu = (float)mu;
    float w = gnw[c] * rs;
    float bias = gnb[c];

    float4 zv = *(const float4*)(d_z + idx);
    float4 xv = *(const float4*)(x + idx);
    float4 o;
    o.x = (zv.x - fmu) * w + bias + xv.x;
    o.y = (zv.y - fmu) * w + bias + xv.y;
    o.z = (zv.z - fmu) * w + bias + xv.z;
    o.w = (zv.w - fmu) * w + bias + xv.w;
    *(float4*)(out + idx) = o;
}

extern "C" void kernel_launch(void* const* d_in, const int* in_sizes, int n_in,
                              void* d_out, int out_size)
{
    const float* x   = (const float*)d_in[0];
    const float* Wt  = (const float*)d_in[1];
    const float* Wp  = (const float*)d_in[2];
    const float* Wg  = (const float*)d_in[3];
    const float* Wz  = (const float*)d_in[4];
    const float* gnw = (const float*)d_in[5];
    const float* gnb = (const float*)d_in[6];
    float* out = (float*)d_out;

    zero_red_kernel<<<1, 128>>>();
    gemm_tpg_kernel<<<dim3(12, 8, 16), 256>>>(Wt, Wp, Wg, x);
    reduce_pg_kernel<<<dim3(64, 16), 256>>>();
    gemm_z_kernel<<<dim3(8, 8, 16), 256>>>(Wz);
    finalize_kernel<<<16384, 256>>>(x, gnw, gnb, out);
}

// round 6
// speedup vs baseline: 1.6553x; 1.6553x over previous
#include <cuda_runtime.h>
#include <cuda_bf16.h>
#include <cstdint>

#define BATCH 16
#define CIN   1024
#define CPD   512
#define SS    1024   // H*W

// ---------------- scratch (device globals) ----------------
__device__ float  d_t[(size_t)BATCH * CPD * SS];
__device__ float  d_p[(size_t)BATCH * CPD * SS];
__device__ float  d_g[(size_t)BATCH * CPD * SS];
__device__ float  d_z[(size_t)BATCH * CIN * SS];
__device__ double d_red[BATCH][8];   // 0..2: Sg,Spg,Sp2g  3,4: sum z, sum z^2

__device__ __nv_bfloat16 d_Whi[(size_t)1536 * CIN];   // Wt|Wp|Wg stacked
__device__ __nv_bfloat16 d_Wlo[(size_t)1536 * CIN];
__device__ __nv_bfloat16 d_Wzhi[(size_t)CIN * CPD];
__device__ __nv_bfloat16 d_Wzlo[(size_t)CIN * CPD];
__device__ __nv_bfloat16 d_xThi[(size_t)BATCH * SS * CIN];  // x^T [b][s][c]
__device__ __nv_bfloat16 d_xTlo[(size_t)BATCH * SS * CIN];
__device__ __nv_bfloat16 d_yThi[(size_t)BATCH * SS * CPD];  // y^T [b][s][cp]
__device__ __nv_bfloat16 d_yTlo[(size_t)BATCH * SS * CPD];

// ---------------- helpers ----------------
__device__ __forceinline__ uint32_t smem_to_u32(const void* p) {
    uint32_t a;
    asm("{ .reg .u64 t; cvta.to.shared.u64 t, %1; cvt.u32.u64 %0, t; }" : "=r"(a) : "l"(p));
    return a;
}
__device__ __forceinline__ void cp16(uint32_t s, const void* g) {
    asm volatile("cp.async.cg.shared.global [%0], [%1], 16;" :: "r"(s), "l"(g));
}
#define CP_COMMIT() asm volatile("cp.async.commit_group;" ::: "memory")
#define CP_WAIT1()  asm volatile("cp.async.wait_group 1;"  ::: "memory")
#define CP_WAIT0()  asm volatile("cp.async.wait_group 0;"  ::: "memory")

__device__ __forceinline__ uint32_t lds32(uint32_t addr) {
    uint32_t v;
    asm volatile("ld.shared.b32 %0, [%1];" : "=r"(v) : "r"(addr));
    return v;
}

// D = A(row) * B(col) + D, bf16 in, fp32 accum
__device__ __forceinline__ void mma16816(float* c, const uint32_t* a, const uint32_t* b) {
    asm volatile(
        "mma.sync.aligned.m16n8k16.row.col.f32.bf16.bf16.f32 "
        "{%0,%1,%2,%3}, {%4,%5,%6,%7}, {%8,%9}, {%0,%1,%2,%3};"
        : "+f"(c[0]), "+f"(c[1]), "+f"(c[2]), "+f"(c[3])
        : "r"(a[0]), "r"(a[1]), "r"(a[2]), "r"(a[3]), "r"(b[0]), "r"(b[1]));
}

// ---------------- SMEM layout ----------------
// Tiles [128 rows][32 halfs], padded row stride 56 halfs (112B):
//  - 112B is 16B-aligned for cp.async
//  - fragment LDS bank = (28*row + q) % 32 -> conflict-free
#define RS_H      56
#define TILE_B    (128 * RS_H * 2)       // 14336 bytes
#define OFF_AHI   0
#define OFF_ALO   (TILE_B)
#define OFF_BHI   (2 * TILE_B)
#define OFF_BLO   (3 * TILE_B)
#define STAGE_B   (4 * TILE_B)           // 57344
#define SMEM_TOTAL (2 * STAGE_B)         // 114688

// ---------------- misc small kernels ----------------
__global__ void zero_red_kernel() {
    int i = threadIdx.x;
    if (i < BATCH * 8) ((double*)d_red)[i] = 0.0;
}

__global__ void split_w_kernel(const float* __restrict__ Wt, const float* __restrict__ Wp,
                               const float* __restrict__ Wg, const float* __restrict__ Wz) {
    size_t i = (size_t)blockIdx.x * 256 + threadIdx.x;
    if (i < (size_t)1536 * CIN) {
        int r = (int)(i >> 10), c = (int)(i & 1023);
        const float* W = (r < 512) ? Wt : ((r < 1024) ? Wp : Wg);
        float v = W[(size_t)(r & 511) * CIN + c];
        __nv_bfloat16 h = __float2bfloat16(v);
        d_Whi[i] = h;
        d_Wlo[i] = __float2bfloat16(v - __bfloat162float(h));
    }
    if (i < (size_t)CIN * CPD) {
        float v = Wz[i];
        __nv_bfloat16 h = __float2bfloat16(v);
        d_Wzhi[i] = h;
        d_Wzlo[i] = __float2bfloat16(v - __bfloat162float(h));
    }
}

// transpose+split x: [b][c][s] fp32 -> [b][s][c] bf16 hi/lo
__global__ void split_x_kernel(const float* __restrict__ x) {
    __shared__ float tile[32][33];
    int b = blockIdx.z, s0 = blockIdx.x * 32, c0 = blockIdx.y * 32;
    int tx = threadIdx.x, ty = threadIdx.y;
    const float* xp = x + ((size_t)b * CIN + c0) * SS + s0;
    for (int i = ty; i < 32; i += 8)
        tile[i][tx] = xp[(size_t)i * SS + tx];          // tile[c][s]
    __syncthreads();
    __nv_bfloat16* oh = d_xThi + ((size_t)b * SS + s0) * CIN + c0;
    __nv_bfloat16* ol = d_xTlo + ((size_t)b * SS + s0) * CIN + c0;
    for (int i = ty; i < 32; i += 8) {
        float v = tile[tx][i];                           // c=c0+tx, s=s0+i
        __nv_bfloat16 h = __float2bfloat16(v);
        oh[(size_t)i * CIN + tx] = h;
        ol[(size_t)i * CIN + tx] = __float2bfloat16(v - __bfloat162float(h));
    }
}

// y = c0 + c1 t + c2 t^2, transposed+split
__global__ void build_y_kernel() {
    __shared__ float tile[32][33];
    int b = blockIdx.z, s0 = blockIdx.x * 32, c0 = blockIdx.y * 32;
    int tx = threadIdx.x, ty = threadIdx.y;
    const double BETA = 0.9998000199986667;  // exp(-2e-4)
    float cf0 = (float)(BETA * d_red[b][0]);
    float cf1 = (float)(2e-4 * BETA * d_red[b][1]);
    float cf2 = (float)(2e-8 * BETA * d_red[b][2]);
    const float* tp = d_t + ((size_t)b * CPD + c0) * SS + s0;
    for (int i = ty; i < 32; i += 8)
        tile[i][tx] = tp[(size_t)i * SS + tx];
    __syncthreads();
    __nv_bfloat16* oh = d_yThi + ((size_t)b * SS + s0) * CPD + c0;
    __nv_bfloat16* ol = d_yTlo + ((size_t)b * SS + s0) * CPD + c0;
    for (int i = ty; i < 32; i += 8) {
        float t = tile[tx][i];
        float y = cf0 + t * (cf1 + cf2 * t);
        __nv_bfloat16 h = __float2bfloat16(y);
        oh[(size_t)i * CPD + tx] = h;
        ol[(size_t)i * CPD + tx] = __float2bfloat16(y - __bfloat162float(h));
    }
}

__global__ void reduce_pg_kernel() {
    const int b = blockIdx.y;
    const float* p = d_p + (size_t)b * CPD * SS;
    const float* g = d_g + (size_t)b * CPD * SS;
    const int n = CPD * SS;
    double s0 = 0, s1 = 0, s2 = 0;
    for (int i = blockIdx.x * blockDim.x + threadIdx.x; i < n; i += gridDim.x * blockDim.x) {
        float pv = p[i], gv = g[i];
        s0 += (double)gv;
        s1 += (double)pv * gv;
        s2 += (double)pv * pv * gv;
    }
    __shared__ double sh0[256], sh1[256], sh2[256];
    sh0[threadIdx.x] = s0; sh1[threadIdx.x] = s1; sh2[threadIdx.x] = s2;
    __syncthreads();
    for (int off = 128; off > 0; off >>= 1) {
        if (threadIdx.x < off) {
            sh0[threadIdx.x] += sh0[threadIdx.x + off];
            sh1[threadIdx.x] += sh1[threadIdx.x + off];
            sh2[threadIdx.x] += sh2[threadIdx.x + off];
        }
        __syncthreads();
    }
    if (threadIdx.x == 0) {
        atomicAdd(&d_red[b][0], sh0[0]);
        atomicAdd(&d_red[b][1], sh1[0]);
        atomicAdd(&d_red[b][2], sh2[0]);
    }
}

// ---------------- HMMA GEMM (WHICH=0: t/p/g, WHICH=1: z) ----------------
// C[128x128] per CTA. A [128][K] row-major (hi/lo), B [128][K] row-major
// (= B^T of the math GEMM; matches mma .row.col with B frag from [n][k]).
template <int WHICH>
__global__ __launch_bounds__(256, 1) void gemm_hmma_kernel() {
    extern __shared__ char smem[];
    const uint32_t sb = smem_to_u32(smem);

    const int tid  = threadIdx.x;
    const int b    = blockIdx.z;
    const int warp = tid >> 5, lane = tid & 31;
    const int wm = warp >> 2, wn = warp & 3;       // 2 x 4 warp grid
    const int grp = lane >> 2, qid = lane & 3;

    constexpr int NK  = (WHICH == 0) ? (CIN / 32) : (CPD / 32);
    constexpr int LDK = (WHICH == 0) ? CIN : CPD;

    const __nv_bfloat16 *gAhi, *gAlo, *gBhi, *gBlo;
    if (WHICH == 0) {
        gAhi = d_Whi + (size_t)blockIdx.x * 128 * CIN;
        gAlo = d_Wlo + (size_t)blockIdx.x * 128 * CIN;
        gBhi = d_xThi + ((size_t)b * SS + (size_t)blockIdx.y * 128) * CIN;
        gBlo = d_xTlo + ((size_t)b * SS + (size_t)blockIdx.y * 128) * CIN;
    } else {
        gAhi = d_Wzhi + (size_t)blockIdx.x * 128 * CPD;
        gAlo = d_Wzlo + (size_t)blockIdx.x * 128 * CPD;
        gBhi = d_yThi + ((size_t)b * SS + (size_t)blockIdx.y * 128) * CPD;
        gBlo = d_yTlo + ((size_t)b * SS + (size_t)blockIdx.y * 128) * CPD;
    }

    float acc[4][4][4];
#pragma unroll
    for (int i = 0; i < 4; i++)
#pragma unroll
        for (int j = 0; j < 4; j++)
#pragma unroll
            for (int v = 0; v < 4; v++) acc[i][j][v] = 0.f;

    // loader: 512 16B-chunks per tensor, 2 per thread per tensor
    auto load_stage = [&](uint32_t s, int k0) {
#pragma unroll
        for (int t = 0; t < 2; t++) {
            int ch  = tid + t * 256;            // 0..511
            int row = ch >> 2, cc = ch & 3;     // cc: 16B chunk within 64B row
            uint32_t so = (uint32_t)(row * (RS_H * 2) + cc * 16);
            size_t   go = (size_t)row * LDK + k0 + cc * 8;
            cp16(s + OFF_AHI + so, gAhi + go);
            cp16(s + OFF_ALO + so, gAlo + go);
            cp16(s + OFF_BHI + so, gBhi + go);
            cp16(s + OFF_BLO + so, gBlo + go);
        }
    };

    load_stage(sb, 0);
    CP_COMMIT();

    for (int k = 0; k < NK; k++) {
        const uint32_t scur = sb + (uint32_t)(k & 1) * STAGE_B;
        if (k + 1 < NK) {
            load_stage(sb + (uint32_t)((k + 1) & 1) * STAGE_B, (k + 1) * 32);
            CP_COMMIT();
            CP_WAIT1();
        } else {
            CP_WAIT0();
        }
        __syncthreads();     // stage k data visible to all warps

#pragma unroll
        for (int kk = 0; kk < 2; kk++) {
            const uint32_t col = (uint32_t)(kk * 16 + qid * 2) * 2;   // bytes
            uint32_t ah[4][4], al[4][4];
#pragma unroll
            for (int mf = 0; mf < 4; mf++) {
                const uint32_t r0 = (uint32_t)(wm * 64 + mf * 16 + grp) * (RS_H * 2);
                const uint32_t r1 = r0 + 8 * (RS_H * 2);
                ah[mf][0] = lds32(scur + OFF_AHI + r0 + col);
                ah[mf][1] = lds32(scur + OFF_AHI + r1 + col);
                ah[mf][2] = lds32(scur + OFF_AHI + r0 + col + 16);
                ah[mf][3] = lds32(scur + OFF_AHI + r1 + col + 16);
                al[mf][0] = lds32(scur + OFF_ALO + r0 + col);
                al[mf][1] = lds32(scur + OFF_ALO + r1 + col);
                al[mf][2] = lds32(scur + OFF_ALO + r0 + col + 16);
                al[mf][3] = lds32(scur + OFF_ALO + r1 + col + 16);
            }
            uint32_t bh[4][2], bl[4][2];
#pragma unroll
            for (int nf = 0; nf < 4; nf++) {
                const uint32_t rn = (uint32_t)(wn * 32 + nf * 8 + grp) * (RS_H * 2);
                bh[nf][0] = lds32(scur + OFF_BHI + rn + col);
                bh[nf][1] = lds32(scur + OFF_BHI + rn + col + 16);
                bl[nf][0] = lds32(scur + OFF_BLO + rn + col);
                bl[nf][1] = lds32(scur + OFF_BLO + rn + col + 16);
            }
#pragma unroll
            for (int mf = 0; mf < 4; mf++)
#pragma unroll
                for (int nf = 0; nf < 4; nf++) {
                    mma16816(acc[mf][nf], ah[mf], bh[nf]);
                    mma16816(acc[mf][nf], ah[mf], bl[nf]);
                    mma16816(acc[mf][nf], al[mf], bh[nf]);
                }
        }
        __syncthreads();     // compute done before next load overwrites scur
    }

    // -------- epilogue: write C[128x128], rows=out-channel, cols=spatial --------
    float* outp;
    if (WHICH == 0) {
        const int mt = blockIdx.x, mat = mt >> 2;
        float* Cb = (mat == 0) ? d_t : ((mat == 1) ? d_p : d_g);
        outp = Cb + ((size_t)b * CPD + (size_t)(mt & 3) * 128) * SS + blockIdx.y * 128;
    } else {
        outp = d_z + ((size_t)b * CIN + (size_t)blockIdx.x * 128) * SS + blockIdx.y * 128;
    }

    double zs = 0.0, zq = 0.0;
#pragma unroll
    for (int mf = 0; mf < 4; mf++) {
        const int r0 = wm * 64 + mf * 16 + grp;
#pragma unroll
        for (int nf = 0; nf < 4; nf++) {
            const int cg = wn * 32 + nf * 8 + qid * 2;
            float2 v0 = {acc[mf][nf][0], acc[mf][nf][1]};
            float2 v1 = {acc[mf][nf][2], acc[mf][nf][3]};
            *(float2*)(outp + (size_t)r0 * SS + cg)       = v0;
            *(float2*)(outp + (size_t)(r0 + 8) * SS + cg) = v1;
            if (WHICH == 1) {
                zs += (double)v0.x + v0.y + (double)v1.x + v1.y;
                zq += (double)v0.x * v0.x + (double)v0.y * v0.y
                    + (double)v1.x * v1.x + (double)v1.y * v1.y;
            }
        }
    }

    if (WHICH == 1) {
        __syncthreads();                       // smem free for reduction
        double* shs = (double*)smem;
        double* shq = shs + 256;
        shs[tid] = zs; shq[tid] = zq;
        __syncthreads();
        for (int off = 128; off > 0; off >>= 1) {
            if (tid < off) { shs[tid] += shs[tid + off]; shq[tid] += shq[tid + off]; }
            __syncthreads();
        }
        if (tid == 0) {
            atomicAdd(&d_red[b][3], shs[0]);
            atomicAdd(&d_red[b][4], shq[0]);
        }
    }
}

// ---------------- finalize: out = (z - mu)*rsigma*gn_w + gn_b + x ----------------
__global__ void finalize_kernel(const float* __restrict__ x,
                                const float* __restrict__ gnw,
                                const float* __restrict__ gnb,
                                float* __restrict__ out) {
    size_t idx4 = (size_t)blockIdx.x * blockDim.x + threadIdx.x;
    const size_t total4 = (size_t)BATCH * CIN * SS / 4;
    if (idx4 >= total4) return;
    size_t idx = idx4 * 4;
    int b = (int)(idx / ((size_t)CIN * SS));
    int c = (int)((idx / SS) % CIN);

    const double n = (double)CIN * SS;
    double mu  = d_red[b][3] / n;
    double var = d_red[b][4] / n - mu * mu;
    float rs  = rsqrtf((float)var + 1e-5f);
    float fmu = (float)mu;
    float w = gnw[c] * rs;
    float bias = gnb[c];

    float4 zv = *(const float4*)(d_z + idx);
    float4 xv = *(const float4*)(x + idx);
    float4 o;
    o.x = (zv.x - fmu) * w + bias + xv.x;
    o.y = (zv.y - fmu) * w + bias + xv.y;
    o.z = (zv.z - fmu) * w + bias + xv.z;
    o.w = (zv.w - fmu) * w + bias + xv.w;
    *(float4*)(out + idx) = o;
}

extern "C" void kernel_launch(void* const* d_in, const int* in_sizes, int n_in,
                              void* d_out, int out_size) {
    const float* x   = (const float*)d_in[0];
    const float* Wt  = (const float*)d_in[1];
    const float* Wp  = (const float*)d_in[2];
    const float* Wg  = (const float*)d_in[3];
    const float* Wz  = (const float*)d_in[4];
    const float* gnw = (const float*)d_in[5];
    const float* gnb = (const float*)d_in[6];
    float* out = (float*)d_out;

    cudaFuncSetAttribute(gemm_hmma_kernel<0>, cudaFuncAttributeMaxDynamicSharedMemorySize, SMEM_TOTAL);
    cudaFuncSetAttribute(gemm_hmma_kernel<1>, cudaFuncAttributeMaxDynamicSharedMemorySize, SMEM_TOTAL);

    zero_red_kernel<<<1, 128>>>();
    split_w_kernel<<<6144, 256>>>(Wt, Wp, Wg, Wz);
    split_x_kernel<<<dim3(32, 32, 16), dim3(32, 8)>>>(x);

    gemm_hmma_kernel<0><<<dim3(12, 8, 16), 256, SMEM_TOTAL>>>();   // t, p, g

    reduce_pg_kernel<<<dim3(64, 16), 256>>>();
    build_y_kernel<<<dim3(32, 16, 16), dim3(32, 8)>>>();

    gemm_hmma_kernel<1><<<dim3(8, 8, 16), 256, SMEM_TOTAL>>>();    // z + GN sums

    finalize_kernel<<<16384, 256>>>(x, gnw, gnb, out);
}

// round 9
// speedup vs baseline: 1.8413x; 1.1124x over previous
#include <cuda_runtime.h>
#include <cuda_bf16.h>
#include <cstdint>

#define BATCH 16
#define CIN   1024
#define CPD   512
#define SS    1024   // H*W

// ---------------- scratch (device globals) ----------------
__device__ float  d_t[(size_t)BATCH * CPD * SS];
__device__ float  d_p[(size_t)BATCH * CPD * SS];
__device__ float  d_g[(size_t)BATCH * CPD * SS];
__device__ float  d_z[(size_t)BATCH * CIN * SS];
__device__ double d_red[BATCH][8];   // 0..2: Sg,Spg,Sp2g  3,4: sum z, sum z^2

__device__ __nv_bfloat16 d_Whi[(size_t)1536 * CIN];   // Wt|Wp|Wg stacked
__device__ __nv_bfloat16 d_Wlo[(size_t)1536 * CIN];
__device__ __nv_bfloat16 d_Wzhi[(size_t)CIN * CPD];
__device__ __nv_bfloat16 d_Wzlo[(size_t)CIN * CPD];
__device__ __nv_bfloat16 d_xThi[(size_t)BATCH * SS * CIN];  // x^T [b][s][c]
__device__ __nv_bfloat16 d_xTlo[(size_t)BATCH * SS * CIN];
__device__ __nv_bfloat16 d_yThi[(size_t)BATCH * SS * CPD];  // y^T [b][s][cp]
__device__ __nv_bfloat16 d_yTlo[(size_t)BATCH * SS * CPD];

// ---------------- helpers ----------------
__device__ __forceinline__ uint32_t smem_to_u32(const void* p) {
    uint32_t a;
    asm("{ .reg .u64 t; cvta.to.shared.u64 t, %1; cvt.u32.u64 %0, t; }" : "=r"(a) : "l"(p));
    return a;
}
__device__ __forceinline__ void cp16(uint32_t s, const void* g) {
    asm volatile("cp.async.cg.shared.global [%0], [%1], 16;" :: "r"(s), "l"(g));
}
#define CP_COMMIT() asm volatile("cp.async.commit_group;" ::: "memory")
#define CP_WAIT1()  asm volatile("cp.async.wait_group 1;"  ::: "memory")
#define CP_WAIT0()  asm volatile("cp.async.wait_group 0;"  ::: "memory")

__device__ __forceinline__ void ldsm4(uint32_t* r, uint32_t addr) {
    asm volatile("ldmatrix.sync.aligned.m8n8.x4.shared.b16 {%0,%1,%2,%3}, [%4];"
                 : "=r"(r[0]), "=r"(r[1]), "=r"(r[2]), "=r"(r[3]) : "r"(addr));
}

// D = A(row) * B(col) + D, bf16 in, fp32 accum
__device__ __forceinline__ void mma16816(float* c, const uint32_t* a, const uint32_t* b) {
    asm volatile(
        "mma.sync.aligned.m16n8k16.row.col.f32.bf16.bf16.f32 "
        "{%0,%1,%2,%3}, {%4,%5,%6,%7}, {%8,%9}, {%0,%1,%2,%3};"
        : "+f"(c[0]), "+f"(c[1]), "+f"(c[2]), "+f"(c[3])
        : "r"(a[0]), "r"(a[1]), "r"(a[2]), "r"(a[3]), "r"(b[0]), "r"(b[1]));
}

// ---------------- SMEM layout ----------------
// Tiles [128 rows][64 halfs], row stride 72 halfs = 144 B:
//  - 16B-aligned for cp.async / ldmatrix
//  - 36-word stride -> ldmatrix 8-row phase hits word offsets 4r mod 32 = all banks
#define RS_B      144
#define TILE_B    (128 * RS_B)           // 18432
#define OFF_AHI   0
#define OFF_ALO   (TILE_B)
#define OFF_BHI   (2 * TILE_B)
#define OFF_BLO   (3 * TILE_B)
#define STAGE_B   (4 * TILE_B)           // 73728
#define NSTAGE    3
#define SMEM_TOTAL (NSTAGE * STAGE_B)    // 221184

// ---------------- misc small kernels ----------------
__global__ void zero_red_kernel() {
    int i = threadIdx.x;
    if (i < BATCH * 8) ((double*)d_red)[i] = 0.0;
}

__global__ void split_w_kernel(const float* __restrict__ Wt, const float* __restrict__ Wp,
                               const float* __restrict__ Wg, const float* __restrict__ Wz) {
    size_t i = (size_t)blockIdx.x * 256 + threadIdx.x;
    if (i < (size_t)1536 * CIN) {
        int r = (int)(i >> 10), c = (int)(i & 1023);
        const float* W = (r < 512) ? Wt : ((r < 1024) ? Wp : Wg);
        float v = W[(size_t)(r & 511) * CIN + c];
        __nv_bfloat16 h = __float2bfloat16(v);
        d_Whi[i] = h;
        d_Wlo[i] = __float2bfloat16(v - __bfloat162float(h));
    }
    if (i < (size_t)CIN * CPD) {
        float v = Wz[i];
        __nv_bfloat16 h = __float2bfloat16(v);
        d_Wzhi[i] = h;
        d_Wzlo[i] = __float2bfloat16(v - __bfloat162float(h));
    }
}

// transpose+split x: [b][c][s] fp32 -> [b][s][c] bf16 hi/lo
__global__ void split_x_kernel(const float* __restrict__ x) {
    __shared__ float tile[32][33];
    int b = blockIdx.z, s0 = blockIdx.x * 32, c0 = blockIdx.y * 32;
    int tx = threadIdx.x, ty = threadIdx.y;
    const float* xp = x + ((size_t)b * CIN + c0) * SS + s0;
    for (int i = ty; i < 32; i += 8)
        tile[i][tx] = xp[(size_t)i * SS + tx];          // tile[c][s]
    __syncthreads();
    __nv_bfloat16* oh = d_xThi + ((size_t)b * SS + s0) * CIN + c0;
    __nv_bfloat16* ol = d_xTlo + ((size_t)b * SS + s0) * CIN + c0;
    for (int i = ty; i < 32; i += 8) {
        float v = tile[tx][i];                           // c=c0+tx, s=s0+i
        __nv_bfloat16 h = __float2bfloat16(v);
        oh[(size_t)i * CIN + tx] = h;
        ol[(size_t)i * CIN + tx] = __float2bfloat16(v - __bfloat162float(h));
    }
}

// y = c0 + c1 t + c2 t^2, transposed+split
__global__ void build_y_kernel() {
    __shared__ float tile[32][33];
    int b = blockIdx.z, s0 = blockIdx.x * 32, c0 = blockIdx.y * 32;
    int tx = threadIdx.x, ty = threadIdx.y;
    const double BETA = 0.9998000199986667;  // exp(-2e-4)
    float cf0 = (float)(BETA * d_red[b][0]);
    float cf1 = (float)(2e-4 * BETA * d_red[b][1]);
    float cf2 = (float)(2e-8 * BETA * d_red[b][2]);
    const float* tp = d_t + ((size_t)b * CPD + c0) * SS + s0;
    for (int i = ty; i < 32; i += 8)
        tile[i][tx] = tp[(size_t)i * SS + tx];
    __syncthreads();
    __nv_bfloat16* oh = d_yThi + ((size_t)b * SS + s0) * CPD + c0;
    __nv_bfloat16* ol = d_yTlo + ((size_t)b * SS + s0) * CPD + c0;
    for (int i = ty; i < 32; i += 8) {
        float t = tile[tx][i];
        float y = cf0 + t * (cf1 + cf2 * t);
        __nv_bfloat16 h = __float2bfloat16(y);
        oh[(size_t)i * CPD + tx] = h;
        ol[(size_t)i * CPD + tx] = __float2bfloat16(y - __bfloat162float(h));
    }
}

__global__ void reduce_pg_kernel() {
    const int b = blockIdx.y;
    const float* p = d_p + (size_t)b * CPD * SS;
    const float* g = d_g + (size_t)b * CPD * SS;
    const int n = CPD * SS;
    double s0 = 0, s1 = 0, s2 = 0;
    for (int i = blockIdx.x * blockDim.x + threadIdx.x; i < n; i += gridDim.x * blockDim.x) {
        float pv = p[i], gv = g[i];
        s0 += (double)gv;
        s1 += (double)pv * gv;
        s2 += (double)pv * pv * gv;
    }
    __shared__ double sh0[256], sh1[256], sh2[256];
    sh0[threadIdx.x] = s0; sh1[threadIdx.x] = s1; sh2[threadIdx.x] = s2;
    __syncthreads();
    for (int off = 128; off > 0; off >>= 1) {
        if (threadIdx.x < off) {
            sh0[threadIdx.x] += sh0[threadIdx.x + off];
            sh1[threadIdx.x] += sh1[threadIdx.x + off];
            sh2[threadIdx.x] += sh2[threadIdx.x + off];
        }
        __syncthreads();
    }
    if (threadIdx.x == 0) {
        atomicAdd(&d_red[b][0], sh0[0]);
        atomicAdd(&d_red[b][1], sh1[0]);
        atomicAdd(&d_red[b][2], sh2[0]);
    }
}

// ---------------- HMMA GEMM (WHICH=0: t/p/g, WHICH=1: z) ----------------
// C[128x128] per CTA. A [128][K] row-major (hi/lo), B [128][K] row-major.
// K-step 64, 3-stage cp.async pipeline, ldmatrix fragment loads.
template <int WHICH>
__global__ __launch_bounds__(256, 1) void gemm_hmma_kernel() {
    extern __shared__ char smem[];
    const uint32_t sb = smem_to_u32(smem);

    const int tid  = threadIdx.x;
    const int b    = blockIdx.z;
    const int warp = tid >> 5, lane = tid & 31;
    const int wm = warp >> 2, wn = warp & 3;       // 2 x 4 warp grid
    const int grp = lane >> 2, qid = lane & 3;
    const int mrow = lane & 7, msel = lane >> 3;   // ldmatrix lane mapping

    constexpr int NK  = (WHICH == 0) ? (CIN / 64) : (CPD / 64);
    constexpr int LDK = (WHICH == 0) ? CIN : CPD;

    const __nv_bfloat16 *gAhi, *gAlo, *gBhi, *gBlo;
    if (WHICH == 0) {
        gAhi = d_Whi + (size_t)blockIdx.x * 128 * CIN;
        gAlo = d_Wlo + (size_t)blockIdx.x * 128 * CIN;
        gBhi = d_xThi + ((size_t)b * SS + (size_t)blockIdx.y * 128) * CIN;
        gBlo = d_xTlo + ((size_t)b * SS + (size_t)blockIdx.y * 128) * CIN;
    } else {
        gAhi = d_Wzhi + (size_t)blockIdx.x * 128 * CPD;
        gAlo = d_Wzlo + (size_t)blockIdx.x * 128 * CPD;
        gBhi = d_yThi + ((size_t)b * SS + (size_t)blockIdx.y * 128) * CPD;
        gBlo = d_yTlo + ((size_t)b * SS + (size_t)blockIdx.y * 128) * CPD;
    }

    float acc[4][4][4];
#pragma unroll
    for (int i = 0; i < 4; i++)
#pragma unroll
        for (int j = 0; j < 4; j++)
#pragma unroll
            for (int v = 0; v < 4; v++) acc[i][j][v] = 0.f;

    // ldmatrix per-lane base offsets (without kk column advance)
    uint32_t aoff[4], boff[2];
#pragma unroll
    for (int mf = 0; mf < 4; mf++)
        aoff[mf] = (uint32_t)(wm * 64 + mf * 16 + (msel & 1) * 8 + mrow) * RS_B
                 + (uint32_t)(msel >> 1) * 16;
#pragma unroll
    for (int nfp = 0; nfp < 2; nfp++)
        boff[nfp] = (uint32_t)(wn * 32 + (2 * nfp + (msel >> 1)) * 8 + mrow) * RS_B
                  + (uint32_t)(msel & 1) * 16;

    // loader: 1024 16B-chunks per tensor (128 rows x 8 chunks), 4 per thread per tensor
    auto load_stage = [&](uint32_t s, int k0) {
#pragma unroll
        for (int i = 0; i < 4; i++) {
            int ch  = tid + i * 256;            // 0..1023
            int row = ch >> 3, cc = ch & 7;
            uint32_t so = (uint32_t)(row * RS_B + cc * 16);
            size_t   go = (size_t)row * LDK + k0 + cc * 8;
            cp16(s + OFF_AHI + so, gAhi + go);
            cp16(s + OFF_ALO + so, gAlo + go);
            cp16(s + OFF_BHI + so, gBhi + go);
            cp16(s + OFF_BLO + so, gBlo + go);
        }
    };

    load_stage(sb, 0);
    CP_COMMIT();
    load_stage(sb + STAGE_B, 64);
    CP_COMMIT();

    for (int k = 0; k < NK; k++) {
        if (k + 1 < NK) { CP_WAIT1(); } else { CP_WAIT0(); }
        __syncthreads();                         // stage k visible; all warps past k-1
        if (k + 2 < NK) {
            load_stage(sb + (uint32_t)((k + 2) % NSTAGE) * STAGE_B, (k + 2) * 64);
            CP_COMMIT();
        }
        const uint32_t scur = sb + (uint32_t)(k % NSTAGE) * STAGE_B;

#pragma unroll
        for (int kk = 0; kk < 4; kk++) {
            const uint32_t col = (uint32_t)kk * 32;
            uint32_t ah[4][4], al[4][4], bh[4][2], bl[4][2];
#pragma unroll
            for (int mf = 0; mf < 4; mf++) {
                ldsm4(ah[mf], scur + OFF_AHI + aoff[mf] + col);
                ldsm4(al[mf], scur + OFF_ALO + aoff[mf] + col);
            }
#pragma unroll
            for (int nfp = 0; nfp < 2; nfp++) {
                uint32_t rb[4];
                ldsm4(rb, scur + OFF_BHI + boff[nfp] + col);
                bh[2 * nfp][0] = rb[0]; bh[2 * nfp][1] = rb[1];
                bh[2 * nfp + 1][0] = rb[2]; bh[2 * nfp + 1][1] = rb[3];
                ldsm4(rb, scur + OFF_BLO + boff[nfp] + col);
                bl[2 * nfp][0] = rb[0]; bl[2 * nfp][1] = rb[1];
                bl[2 * nfp + 1][0] = rb[2]; bl[2 * nfp + 1][1] = rb[3];
            }
#pragma unroll
            for (int mf = 0; mf < 4; mf++)
#pragma unroll
                for (int nf = 0; nf < 4; nf++) {
                    mma16816(acc[mf][nf], ah[mf], bh[nf]);
                    mma16816(acc[mf][nf], ah[mf], bl[nf]);
                    mma16816(acc[mf][nf], al[mf], bh[nf]);
                }
        }
        // no trailing sync: next iteration's sync protects buffer reuse
    }

    // -------- epilogue: write C[128x128], rows=out-channel, cols=spatial --------
    float* outp;
    if (WHICH == 0) {
        const int mt = blockIdx.x, mat = mt >> 2;
        float* Cb = (mat == 0) ? d_t : ((mat == 1) ? d_p : d_g);
        outp = Cb + ((size_t)b * CPD + (size_t)(mt & 3) * 128) * SS + blockIdx.y * 128;
    } else {
        outp = d_z + ((size_t)b * CIN + (size_t)blockIdx.x * 128) * SS + blockIdx.y * 128;
    }

    double zs = 0.0, zq = 0.0;
#pragma unroll
    for (int mf = 0; mf < 4; mf++) {
        const int r0 = wm * 64 + mf * 16 + grp;
#pragma unroll
        for (int nf = 0; nf < 4; nf++) {
            const int cg = wn * 32 + nf * 8 + qid * 2;
            float2 v0 = {acc[mf][nf][0], acc[mf][nf][1]};
            float2 v1 = {acc[mf][nf][2], acc[mf][nf][3]};
            *(float2*)(outp + (size_t)r0 * SS + cg)       = v0;
            *(float2*)(outp + (size_t)(r0 + 8) * SS + cg) = v1;
            if (WHICH == 1) {
                zs += (double)v0.x + v0.y + (double)v1.x + v1.y;
                zq += (double)v0.x * v0.x + (double)v0.y * v0.y
                    + (double)v1.x * v1.x + (double)v1.y * v1.y;
            }
        }
    }

    if (WHICH == 1) {
        __syncthreads();                       // smem free for reduction
        double* shs = (double*)smem;
        double* shq = shs + 256;
        shs[tid] = zs; shq[tid] = zq;
        __syncthreads();
        for (int off = 128; off > 0; off >>= 1) {
            if (tid < off) { shs[tid] += shs[tid + off]; shq[tid] += shq[tid + off]; }
            __syncthreads();
        }
        if (tid == 0) {
            atomicAdd(&d_red[b][3], shs[0]);
            atomicAdd(&d_red[b][4], shq[0]);
        }
    }
}

// ---------------- finalize: out = (z - mu)*rsigma*gn_w + gn_b + x ----------------
__global__ void finalize_kernel(const float* __restrict__ x,
                                const float* __restrict__ gnw,
                                const float* __restrict__ gnb,
                                float* __restrict__ out) {
    size_t idx4 = (size_t)blockIdx.x * blockDim.x + threadIdx.x;
    const size_t total4 = (size_t)BATCH * CIN * SS / 4;
    if (idx4 >= total4) return;
    size_t idx = idx4 * 4;
    int b = (int)(idx / ((size_t)CIN * SS));
    int c = (int)((idx / SS) % CIN);

    const double n = (double)CIN * SS;
    double mu  = d_red[b][3] / n;
    double var = d_red[b][4] / n - mu * mu;
    float rs  = rsqrtf((float)var + 1e-5f);
    float fmu = (float)mu;
    float w = gnw[c] * rs;
    float bias = gnb[c];

    float4 zv = *(const float4*)(d_z + idx);
    float4 xv = *(const float4*)(x + idx);
    float4 o;
    o.x = (zv.x - fmu) * w + bias + xv.x;
    o.y = (zv.y - fmu) * w + bias + xv.y;
    o.z = (zv.z - fmu) * w + bias + xv.z;
    o.w = (zv.w - fmu) * w + bias + xv.w;
    *(float4*)(out + idx) = o;
}

extern "C" void kernel_launch(void* const* d_in, const int* in_sizes, int n_in,
                              void* d_out, int out_size) {
    const float* x   = (const float*)d_in[0];
    const float* Wt  = (const float*)d_in[1];
    const float* Wp  = (const float*)d_in[2];
    const float* Wg  = (const float*)d_in[3];
    const float* Wz  = (const float*)d_in[4];
    const float* gnw = (const float*)d_in[5];
    const float* gnb = (const float*)d_in[6];
    float* out = (float*)d_out;

    cudaFuncSetAttribute(gemm_hmma_kernel<0>, cudaFuncAttributeMaxDynamicSharedMemorySize, SMEM_TOTAL);
    cudaFuncSetAttribute(gemm_hmma_kernel<1>, cudaFuncAttributeMaxDynamicSharedMemorySize, SMEM_TOTAL);

    zero_red_kernel<<<1, 128>>>();
    split_w_kernel<<<6144, 256>>>(Wt, Wp, Wg, Wz);
    split_x_kernel<<<dim3(32, 32, 16), dim3(32, 8)>>>(x);

    gemm_hmma_kernel<0><<<dim3(12, 8, 16), 256, SMEM_TOTAL>>>();   // t, p, g

    reduce_pg_kernel<<<dim3(64, 16), 256>>>();
    build_y_kernel<<<dim3(32, 16, 16), dim3(32, 8)>>>();

    gemm_hmma_kernel<1><<<dim3(8, 8, 16), 256, SMEM_TOTAL>>>();    // z + GN sums

    finalize_kernel<<<16384, 256>>>(x, gnw, gnb, out);
}